// round 1
// baseline (speedup 1.0000x reference)
#include <cuda_runtime.h>
#include <math.h>

// Problem constants (fixed by the dataset)
#define BCNT 16
#define QLEN 4096
#define KLEN 4096
#define DIM  256
#define NQROWS (BCNT*QLEN)   // 65536
#define NKROWS (BCNT*KLEN)   // 65536

// ---------------- scratch (static device globals; no allocs allowed) ------------
__device__ float g_qp [NQROWS*DIM];      // phi(q)  64 MB
__device__ float g_kp [NKROWS*DIM];      // phi(k)  64 MB
__device__ float g_nq [NQROWS];          // per-row exponent offset for q
__device__ float g_nk [NKROWS];          // per-row exponent offset for k
__device__ float g_b1v[BCNT*DIM*DIM];    // buf1 value part  [b][m][c]
__device__ float g_b1s[BCNT*DIM];        // buf1 ones column [b][m]
__device__ float g_den[NQROWS];          // denominator per q row

// ---------------- row norms: s[r] = -0.03125*||row||^2 - ln(16) ---------------
// (x = row * 0.25  =>  -0.5*||x||^2 = -0.03125*||row||^2 ; 1/sqrt(m)=1/16)
__global__ void rownorm_kernel(const float* __restrict__ X, int which /*0=q,1=k*/) {
    int warp = (blockIdx.x * blockDim.x + threadIdx.x) >> 5;
    int lane = threadIdx.x & 31;
    const float4* row = (const float4*)(X + (size_t)warp * DIM);
    float4 a = row[lane * 2];
    float4 b = row[lane * 2 + 1];
    float s = a.x*a.x + a.y*a.y + a.z*a.z + a.w*a.w
            + b.x*b.x + b.y*b.y + b.z*b.z + b.w*b.w;
    #pragma unroll
    for (int o = 16; o; o >>= 1) s += __shfl_xor_sync(0xFFFFFFFFu, s, o);
    if (lane == 0) {
        float v = -0.03125f * s - 2.7725887222397811f;
        if (which) g_nk[warp] = v; else g_nq[warp] = v;
    }
}

// ---------------- phi GEMM: out[r][n] = exp(0.25*dot(X[r],proj[n]) + s[r]) -----
// 128x128 tile, BK=16, 256 threads, 8x8 micro-tile.
__global__ void __launch_bounds__(256) phi_gemm(const float* __restrict__ X,
                                                const float* __restrict__ proj,
                                                int which /*0=q,1=k*/) {
    __shared__ float As[16 * 132];
    __shared__ float Bs[16 * 132];
    const int tid = threadIdx.x;
    const int tx  = tid & 15;
    const int ty  = tid >> 4;
    const int row0 = blockIdx.y * 128;
    const int col0 = blockIdx.x * 128;

    float acc[8][8];
    #pragma unroll
    for (int i = 0; i < 8; i++)
        #pragma unroll
        for (int j = 0; j < 8; j++) acc[i][j] = 0.f;

    for (int k0 = 0; k0 < DIM; k0 += 16) {
        #pragma unroll
        for (int l = 0; l < 2; l++) {
            int idx = tid + l * 256;          // 0..511
            int r   = idx >> 2;               // 0..127
            int kq  = (idx & 3) * 4;          // 0,4,8,12
            float4 va = *(const float4*)(X    + (size_t)(row0 + r) * DIM + k0 + kq);
            As[(kq+0)*132 + r] = va.x;
            As[(kq+1)*132 + r] = va.y;
            As[(kq+2)*132 + r] = va.z;
            As[(kq+3)*132 + r] = va.w;
            float4 vb = *(const float4*)(proj + (size_t)(col0 + r) * DIM + k0 + kq);
            Bs[(kq+0)*132 + r] = vb.x;
            Bs[(kq+1)*132 + r] = vb.y;
            Bs[(kq+2)*132 + r] = vb.z;
            Bs[(kq+3)*132 + r] = vb.w;
        }
        __syncthreads();
        #pragma unroll
        for (int kk = 0; kk < 16; kk++) {
            float a[8], b[8];
            float4 t;
            t = *(const float4*)&As[kk*132 + ty*8    ]; a[0]=t.x; a[1]=t.y; a[2]=t.z; a[3]=t.w;
            t = *(const float4*)&As[kk*132 + ty*8 + 4]; a[4]=t.x; a[5]=t.y; a[6]=t.z; a[7]=t.w;
            t = *(const float4*)&Bs[kk*132 + tx*8    ]; b[0]=t.x; b[1]=t.y; b[2]=t.z; b[3]=t.w;
            t = *(const float4*)&Bs[kk*132 + tx*8 + 4]; b[4]=t.x; b[5]=t.y; b[6]=t.z; b[7]=t.w;
            #pragma unroll
            for (int i = 0; i < 8; i++)
                #pragma unroll
                for (int j = 0; j < 8; j++)
                    acc[i][j] = fmaf(a[i], b[j], acc[i][j]);
        }
        __syncthreads();
    }

    float* out = which ? g_kp : g_qp;
    const float* nrm = which ? g_nk : g_nq;
    #pragma unroll
    for (int i = 0; i < 8; i++) {
        int r = row0 + ty*8 + i;
        float s = nrm[r];
        #pragma unroll
        for (int j = 0; j < 8; j++) {
            out[(size_t)r * DIM + col0 + tx*8 + j] = expf(0.25f * acc[i][j] + s);
        }
    }
}

// ---------------- zero buf1 scratch --------------------------------------------
__global__ void zero_kernel() {
    int n1 = BCNT * DIM * DIM;
    int n2 = BCNT * DIM;
    for (int i = blockIdx.x * blockDim.x + threadIdx.x; i < n1; i += gridDim.x * blockDim.x)
        g_b1v[i] = 0.f;
    for (int i = blockIdx.x * blockDim.x + threadIdx.x; i < n2; i += gridDim.x * blockDim.x)
        g_b1s[i] = 0.f;
}

// ---------------- buf1_v[b][m][c] += sum_{k<valid} kp[b][k][m]*vs[b][k][c] -----
// grid: x = 16 tiles (mt*4+ct, 64x64), y = batch, z = ksplit(8, chunks of 512)
__global__ void __launch_bounds__(256) buf1_kernel(const float* __restrict__ vs,
                                                   const int*   __restrict__ vlen) {
    __shared__ float As[16 * 68];
    __shared__ float Bs[16 * 68];
    const int b  = blockIdx.y;
    const int ks = blockIdx.z;
    const int m0 = (blockIdx.x >> 2) * 64;
    const int c0 = (blockIdx.x &  3) * 64;
    const int kbeg = ks * 512;
    const int kend = min(vlen[b], kbeg + 512);
    if (kbeg >= kend) return;

    const int tid = threadIdx.x;
    const int tx  = tid & 15;
    const int ty  = tid >> 4;
    const float* kpb = g_kp + (size_t)b * KLEN * DIM;
    const float* vsb = vs   + (size_t)b * KLEN * DIM;

    float acc[4][4];
    #pragma unroll
    for (int i = 0; i < 4; i++)
        #pragma unroll
        for (int j = 0; j < 4; j++) acc[i][j] = 0.f;

    const int kl = tid >> 4;          // 0..15 (k within tile)
    const int mq = (tid & 15) * 4;    // 0..60

    for (int k0 = kbeg; k0 < kend; k0 += 16) {
        int gk = k0 + kl;
        float4 va, vb;
        if (gk < kend) {
            va = *(const float4*)(kpb + (size_t)gk * DIM + m0 + mq);
            vb = *(const float4*)(vsb + (size_t)gk * DIM + c0 + mq);
        } else {
            va = make_float4(0.f,0.f,0.f,0.f);
            vb = make_float4(0.f,0.f,0.f,0.f);
        }
        *(float4*)&As[kl*68 + mq] = va;
        *(float4*)&Bs[kl*68 + mq] = vb;
        __syncthreads();
        #pragma unroll
        for (int kk = 0; kk < 16; kk++) {
            float4 a4 = *(const float4*)&As[kk*68 + ty*4];
            float4 b4 = *(const float4*)&Bs[kk*68 + tx*4];
            float a[4] = {a4.x, a4.y, a4.z, a4.w};
            float bb[4] = {b4.x, b4.y, b4.z, b4.w};
            #pragma unroll
            for (int i = 0; i < 4; i++)
                #pragma unroll
                for (int j = 0; j < 4; j++)
                    acc[i][j] = fmaf(a[i], bb[j], acc[i][j]);
        }
        __syncthreads();
    }
    #pragma unroll
    for (int i = 0; i < 4; i++)
        #pragma unroll
        for (int j = 0; j < 4; j++)
            atomicAdd(&g_b1v[((size_t)b * DIM + m0 + ty*4 + i) * DIM + c0 + tx*4 + j],
                      acc[i][j]);
}

// ---------------- buf1_s[b][m] += sum_{k<valid} kp[b][k][m] -------------------
__global__ void buf1s_kernel(const int* __restrict__ vlen) {
    const int b  = blockIdx.y;
    const int ks = blockIdx.x;
    const int m  = threadIdx.x;
    const int kbeg = ks * 512;
    const int kend = min(vlen[b], kbeg + 512);
    if (kbeg >= kend) return;
    const float* kpb = g_kp + (size_t)b * KLEN * DIM;
    float acc = 0.f;
    for (int k = kbeg; k < kend; k++)
        acc += kpb[(size_t)k * DIM + m];
    atomicAdd(&g_b1s[b * DIM + m], acc);
}

// ---------------- den[r] = dot(qp[r], b1s[b]) ---------------------------------
__global__ void den_kernel() {
    int warp = (blockIdx.x * blockDim.x + threadIdx.x) >> 5;
    int lane = threadIdx.x & 31;
    int b = warp >> 12;   // 4096 rows per batch
    const float4* q4 = (const float4*)(g_qp + (size_t)warp * DIM);
    const float4* s4 = (const float4*)(g_b1s + b * DIM);
    float4 qa = q4[lane*2],   qb = q4[lane*2+1];
    float4 sa = s4[lane*2],   sb = s4[lane*2+1];
    float s = qa.x*sa.x + qa.y*sa.y + qa.z*sa.z + qa.w*sa.w
            + qb.x*sb.x + qb.y*sb.y + qb.z*sb.z + qb.w*sb.w;
    #pragma unroll
    for (int o = 16; o; o >>= 1) s += __shfl_xor_sync(0xFFFFFFFFu, s, o);
    if (lane == 0) g_den[warp] = s;
}

// ---------------- ctx GEMM: out[r][c] = dot(qp[r], b1v[b][:,c]) / den[r] -------
__global__ void __launch_bounds__(256) ctx_gemm(float* __restrict__ out) {
    __shared__ float As[16 * 132];
    __shared__ float Bs[16 * 132];
    const int tid = threadIdx.x;
    const int tx  = tid & 15;
    const int ty  = tid >> 4;
    const int row0 = blockIdx.y * 128;
    const int col0 = blockIdx.x * 128;
    const int b = row0 >> 12;
    const float* Bm = g_b1v + (size_t)b * DIM * DIM;

    float acc[8][8];
    #pragma unroll
    for (int i = 0; i < 8; i++)
        #pragma unroll
        for (int j = 0; j < 8; j++) acc[i][j] = 0.f;

    for (int k0 = 0; k0 < DIM; k0 += 16) {
        #pragma unroll
        for (int l = 0; l < 2; l++) {
            int idx = tid + l * 256;
            // A tile (transpose into smem)
            int r  = idx >> 2;
            int kq = (idx & 3) * 4;
            float4 va = *(const float4*)(g_qp + (size_t)(row0 + r) * DIM + k0 + kq);
            As[(kq+0)*132 + r] = va.x;
            As[(kq+1)*132 + r] = va.y;
            As[(kq+2)*132 + r] = va.z;
            As[(kq+3)*132 + r] = va.w;
            // B tile (row-major direct)
            int kb = idx >> 5;            // 0..15
            int nq = (idx & 31) * 4;      // 0..124
            float4 vb = *(const float4*)(Bm + (size_t)(k0 + kb) * DIM + col0 + nq);
            *(float4*)&Bs[kb*132 + nq] = vb;
        }
        __syncthreads();
        #pragma unroll
        for (int kk = 0; kk < 16; kk++) {
            float a[8], bb[8];
            float4 t;
            t = *(const float4*)&As[kk*132 + ty*8    ]; a[0]=t.x; a[1]=t.y; a[2]=t.z; a[3]=t.w;
            t = *(const float4*)&As[kk*132 + ty*8 + 4]; a[4]=t.x; a[5]=t.y; a[6]=t.z; a[7]=t.w;
            t = *(const float4*)&Bs[kk*132 + tx*8    ]; bb[0]=t.x; bb[1]=t.y; bb[2]=t.z; bb[3]=t.w;
            t = *(const float4*)&Bs[kk*132 + tx*8 + 4]; bb[4]=t.x; bb[5]=t.y; bb[6]=t.z; bb[7]=t.w;
            #pragma unroll
            for (int i = 0; i < 8; i++)
                #pragma unroll
                for (int j = 0; j < 8; j++)
                    acc[i][j] = fmaf(a[i], bb[j], acc[i][j]);
        }
        __syncthreads();
    }
    #pragma unroll
    for (int i = 0; i < 8; i++) {
        int r = row0 + ty*8 + i;
        float d = g_den[r];
        #pragma unroll
        for (int j = 0; j < 8; j++) {
            out[(size_t)r * DIM + col0 + tx*8 + j] = acc[i][j] / d;
        }
    }
}

// ---------------- launch -------------------------------------------------------
extern "C" void kernel_launch(void* const* d_in, const int* in_sizes, int n_in,
                              void* d_out, int out_size) {
    (void)in_sizes; (void)n_in; (void)out_size;
    const float* qs   = (const float*)d_in[0];
    const float* ks   = (const float*)d_in[1];
    const float* vs   = (const float*)d_in[2];
    const int*   vlen = (const int*)  d_in[3];
    const float* proj = (const float*)d_in[4];
    float* out = (float*)d_out;

    // 1) per-row exponent offsets
    rownorm_kernel<<<NQROWS/8, 256>>>(qs, 0);
    rownorm_kernel<<<NKROWS/8, 256>>>(ks, 1);

    // 2) phi projections (dominant GEMMs)
    phi_gemm<<<dim3(DIM/128, NQROWS/128), 256>>>(qs, proj, 0);
    phi_gemm<<<dim3(DIM/128, NKROWS/128), 256>>>(ks, proj, 1);

    // 3) zero split-K accumulators (fresh every replay)
    zero_kernel<<<1024, 256>>>();

    // 4) buf1 reductions over valid k
    buf1_kernel<<<dim3(16, BCNT, 8), 256>>>(vs, vlen);
    buf1s_kernel<<<dim3(8, BCNT), 256>>>(vlen);

    // 5) denominators
    den_kernel<<<NQROWS/8, 256>>>();

    // 6) final context GEMM + divide
    ctx_gemm<<<dim3(DIM/128, NQROWS/128), 256>>>(out);
}